// round 16
// baseline (speedup 1.0000x reference)
#include <cuda_runtime.h>
#include <cuda_fp16.h>
#include <cuda_bf16.h>
#include <cstdint>

// Problem constants: N_NODES=50000, N_EDGES=640000, D=128, OUT=1
#define MAX_NODES 50000
#define D 128
#define TABLE_BYTES (MAX_NODES * 4)   // 200000 B of __half2
#define FILL_CHUNK 50000              // 4 chunks of 50000 B (16B multiple)
#define EDGE_BLOCKS 152
#define NODE_BLOCKS 152
#define QUADS_PER_THREAD 2

// Packed per-node projections: lo = dot(X[n],W1), hi = dot(X[n],W2), fp16.
__device__ __align__(16) __half2 d_pack[MAX_NODES];

__device__ __forceinline__ float dot4(float4 a, float4 b) {
    return a.x * b.x + a.y * b.y + a.z * b.z + a.w * b.w;
}

// Kernel 1: 152 blocks x 1024 threads (one CTA/SM, single wave) grid-striding
// over 256-row tiles; 8 rows/warp, 8 lanes/row, fully-coalesced front-batched
// LDG.128 x8. oe=1 kills the cross-CTA L1tex-queue contention spread that the
// 782-small-CTA version suffered.
__global__ void __launch_bounds__(1024, 1)
node_proj_kernel(const float* __restrict__ X,
                 const float* __restrict__ W1,
                 const float* __restrict__ W2,
                 int n_nodes) {
    __shared__ __align__(16) float sW1[D];
    __shared__ __align__(16) float sW2[D];
    int tid = threadIdx.x;
    if (tid < D) {
        sW1[tid] = W1[tid];
        sW2[tid] = W2[tid];
    }
    __syncthreads();

    int lane = tid & 31;
    int sub  = lane & 7;
    int grp  = lane >> 3;
    int wid  = tid >> 5;                        // 0..31

    const float4* Xv = reinterpret_cast<const float4*>(X);
    const float4* w1 = reinterpret_cast<const float4*>(sW1);
    const float4* w2 = reinterpret_cast<const float4*>(sW2);
    float4 w1_0 = w1[sub], w1_1 = w1[sub + 8], w1_2 = w1[sub + 16], w1_3 = w1[sub + 24];
    float4 w2_0 = w2[sub], w2_1 = w2[sub + 8], w2_2 = w2[sub + 16], w2_3 = w2[sub + 24];

    int rows_per_block = 32 * 8;                // 256 rows per block-iteration
    int n_tiles = (n_nodes + rows_per_block - 1) / rows_per_block;   // 196

    for (int t = blockIdx.x; t < n_tiles; t += gridDim.x) {
        int n0 = t * rows_per_block + wid * 8;
        int rowA = n0 + grp;
        int rowB = n0 + 4 + grp;

        float sA1 = 0.f, sA2 = 0.f, sB1 = 0.f, sB2 = 0.f;
        if (rowA < n_nodes) {
            float4 a0 = Xv[(size_t)rowA * 32 + sub + 0];
            float4 a1 = Xv[(size_t)rowA * 32 + sub + 8];
            float4 a2 = Xv[(size_t)rowA * 32 + sub + 16];
            float4 a3 = Xv[(size_t)rowA * 32 + sub + 24];
            sA1 = dot4(a0, w1_0) + dot4(a1, w1_1) + dot4(a2, w1_2) + dot4(a3, w1_3);
            sA2 = dot4(a0, w2_0) + dot4(a1, w2_1) + dot4(a2, w2_2) + dot4(a3, w2_3);
        }
        if (rowB < n_nodes) {
            float4 b0 = Xv[(size_t)rowB * 32 + sub + 0];
            float4 b1 = Xv[(size_t)rowB * 32 + sub + 8];
            float4 b2 = Xv[(size_t)rowB * 32 + sub + 16];
            float4 b3 = Xv[(size_t)rowB * 32 + sub + 24];
            sB1 = dot4(b0, w1_0) + dot4(b1, w1_1) + dot4(b2, w1_2) + dot4(b3, w1_3);
            sB2 = dot4(b0, w2_0) + dot4(b1, w2_1) + dot4(b2, w2_2) + dot4(b3, w2_3);
        }

        #pragma unroll
        for (int off = 4; off > 0; off >>= 1) {
            sA1 += __shfl_xor_sync(0xFFFFFFFF, sA1, off);
            sA2 += __shfl_xor_sync(0xFFFFFFFF, sA2, off);
            sB1 += __shfl_xor_sync(0xFFFFFFFF, sB1, off);
            sB2 += __shfl_xor_sync(0xFFFFFFFF, sB2, off);
        }

        if (sub == 0) {
            if (rowA < n_nodes) d_pack[rowA] = __floats2half2_rn(sA1, sA2);
            if (rowB < n_nodes) d_pack[rowB] = __floats2half2_rn(sB1, sB2);
        }
    }
}

#define CLAMP(v) min(max((v), 0), MAX_NODES - 1)

// Kernel 2 (exact R9 best): cp.async.bulk table fill, indices prefetched
// before the mbarrier wait, pure-LDS gathers after.
__global__ void __launch_bounds__(1024, 1)
edge_kernel_pack(const int* __restrict__ ei,
                 float* __restrict__ out,
                 int n_edges) {
    extern __shared__ __align__(16) unsigned char smem_raw[];
    __half2* s_p = reinterpret_cast<__half2*>(smem_raw);

    uint32_t smem_base;
    asm("{ .reg .u64 t; cvta.to.shared.u64 t, %1; cvt.u32.u64 %0, t; }"
        : "=r"(smem_base) : "l"(smem_raw));
    uint32_t mbar = smem_base + TABLE_BYTES;

    int tid = threadIdx.x;

    if (tid == 0) {
        asm volatile("mbarrier.init.shared.b64 [%0], 1;" :: "r"(mbar) : "memory");
    }
    __syncthreads();

    if (tid == 0) {
        asm volatile("mbarrier.arrive.expect_tx.shared.b64 _, [%0], %1;"
                     :: "r"(mbar), "r"((uint32_t)TABLE_BYTES) : "memory");
        const char* src = reinterpret_cast<const char*>(d_pack);
        #pragma unroll
        for (int c = 0; c < 4; c++) {
            asm volatile(
                "cp.async.bulk.shared::cta.global.mbarrier::complete_tx::bytes "
                "[%0], [%1], %2, [%3];"
                :: "r"(smem_base + c * FILL_CHUNK), "l"(src + (size_t)c * FILL_CHUNK),
                   "r"((uint32_t)FILL_CHUNK), "r"(mbar) : "memory");
        }
    }

    // ---- Prefetch ALL edge indices (overlaps the bulk fill) ----
    int total_quads = n_edges >> 2;                   // 160000
    int qpb = (total_quads + gridDim.x - 1) / gridDim.x;
    int q_start = blockIdx.x * qpb;
    int q_end = min(q_start + qpb, total_quads);

    int  qs[QUADS_PER_THREAD];
    bool qv[QUADS_PER_THREAD];
    int4 sA[QUADS_PER_THREAD], dA[QUADS_PER_THREAD];
    #pragma unroll
    for (int k = 0; k < QUADS_PER_THREAD; k++) {
        int q = q_start + tid + k * 1024;
        qs[k] = q;
        qv[k] = q < q_end;
        if (qv[k]) {
            sA[k] = *reinterpret_cast<const int4*>(ei + q * 4);
            dA[k] = *reinterpret_cast<const int4*>(ei + n_edges + q * 4);
        }
    }

    // ---- Wait for the table ----
    {
        uint32_t done;
        asm volatile(
            "{\n\t"
            ".reg .pred p;\n\t"
            "mbarrier.try_wait.parity.acquire.cta.shared::cta.b64 p, [%1], 0;\n\t"
            "selp.b32 %0, 1, 0, p;\n\t"
            "}"
            : "=r"(done) : "r"(mbar) : "memory");
        if (!done) {
            asm volatile(
                "{\n\t"
                ".reg .pred P1;\n\t"
                "WL_%=:\n\t"
                "mbarrier.try_wait.parity.acquire.cta.shared::cta.b64 P1, [%0], 0, 0x989680;\n\t"
                "@P1 bra.uni WD_%=;\n\t"
                "bra.uni WL_%=;\n\t"
                "WD_%=:\n\t"
                "}"
                :: "r"(mbar) : "memory");
        }
    }

    // ---- Gather + store ----
    #pragma unroll
    for (int k = 0; k < QUADS_PER_THREAD; k++) {
        if (qv[k]) {
            float4 r;
            r.x = __low2float(s_p[CLAMP(sA[k].x)]) + __high2float(s_p[CLAMP(dA[k].x)]);
            r.y = __low2float(s_p[CLAMP(sA[k].y)]) + __high2float(s_p[CLAMP(dA[k].y)]);
            r.z = __low2float(s_p[CLAMP(sA[k].z)]) + __high2float(s_p[CLAMP(dA[k].z)]);
            r.w = __low2float(s_p[CLAMP(sA[k].w)]) + __high2float(s_p[CLAMP(dA[k].w)]);
            *reinterpret_cast<float4*>(out + qs[k] * 4) = r;
        }
    }

    // Scalar tail (n_edges % 4 != 0) — block 0 only.
    if (blockIdx.x == 0) {
        for (int e = total_quads * 4 + tid; e < n_edges; e += blockDim.x) {
            int s = CLAMP(ei[e]);
            int d = CLAMP(ei[n_edges + e]);
            out[e] = __low2float(s_p[s]) + __high2float(s_p[d]);
        }
    }
}

extern "C" void kernel_launch(void* const* d_in, const int* in_sizes, int n_in,
                              void* d_out, int out_size) {
    const float* X  = (const float*)d_in[0];
    const int*   ei = (const int*)d_in[1];     // [2, E] int32
    const float* W1 = (const float*)d_in[2];
    const float* W2 = (const float*)d_in[3];
    float* out = (float*)d_out;

    int n_nodes = in_sizes[0] / D;             // 50000
    int n_edges = in_sizes[1] / 2;             // 640000

    static int inited = 0;
    if (!inited) {
        inited = 1;
        cudaFuncSetAttribute(edge_kernel_pack,
                             cudaFuncAttributeMaxDynamicSharedMemorySize,
                             TABLE_BYTES + 16);
    }

    // Kernel 1: one CTA per SM, single wave, grid-stride.
    node_proj_kernel<<<NODE_BLOCKS, 1024>>>(X, W1, W2, n_nodes);

    // Kernel 2: one block per SM; table + mbarrier in smem.
    size_t smem = TABLE_BYTES + 16;
    edge_kernel_pack<<<EDGE_BLOCKS, 1024, smem>>>(ei, out, n_edges);
}

// round 17
// speedup vs baseline: 1.1910x; 1.1910x over previous
#include <cuda_runtime.h>
#include <cuda_fp16.h>
#include <cuda_bf16.h>
#include <cstdint>

// Problem constants: N_NODES=50000, N_EDGES=640000, D=128, OUT=1
#define MAX_NODES 50000
#define D 128
#define TABLE_BYTES (MAX_NODES * 4)   // 200000 B of __half2
#define FILL_CHUNK 50000              // 4 chunks of 50000 B (16B multiple)
#define EDGE_BLOCKS 152
#define QUADS_PER_THREAD 2

// Packed per-node projections: lo = dot(X[n],W1), hi = dot(X[n],W2), fp16.
__device__ __align__(16) __half2 d_pack[MAX_NODES];

__device__ __forceinline__ float dot4(float4 a, float4 b) {
    return a.x * b.x + a.y * b.y + a.z * b.z + a.w * b.w;
}

// Kernel 1 (R9-proven, fine-grained 782x256 self-balancing): 8 rows/warp,
// 8 lanes/row, fully-coalesced front-batched LDG.128 x8.
__global__ void node_proj_kernel(const float* __restrict__ X,
                                 const float* __restrict__ W1,
                                 const float* __restrict__ W2,
                                 int n_nodes) {
    __shared__ __align__(16) float sW1[D];
    __shared__ __align__(16) float sW2[D];
    int tid = threadIdx.x;
    if (tid < D) {
        sW1[tid] = W1[tid];
        sW2[tid] = W2[tid];
    }
    __syncthreads();

    int lane = tid & 31;
    int sub  = lane & 7;
    int grp  = lane >> 3;
    int gwarp = (blockIdx.x * blockDim.x + tid) >> 5;
    int n0 = gwarp * 8;
    if (n0 >= n_nodes) return;

    int rowA = n0 + grp;
    int rowB = n0 + 4 + grp;

    const float4* Xv = reinterpret_cast<const float4*>(X);
    float4 a0 = Xv[(size_t)rowA * 32 + sub + 0];
    float4 a1 = Xv[(size_t)rowA * 32 + sub + 8];
    float4 a2 = Xv[(size_t)rowA * 32 + sub + 16];
    float4 a3 = Xv[(size_t)rowA * 32 + sub + 24];
    float4 b0 = Xv[(size_t)rowB * 32 + sub + 0];
    float4 b1 = Xv[(size_t)rowB * 32 + sub + 8];
    float4 b2 = Xv[(size_t)rowB * 32 + sub + 16];
    float4 b3 = Xv[(size_t)rowB * 32 + sub + 24];

    const float4* w1 = reinterpret_cast<const float4*>(sW1);
    const float4* w2 = reinterpret_cast<const float4*>(sW2);
    float4 w1_0 = w1[sub], w1_1 = w1[sub + 8], w1_2 = w1[sub + 16], w1_3 = w1[sub + 24];
    float4 w2_0 = w2[sub], w2_1 = w2[sub + 8], w2_2 = w2[sub + 16], w2_3 = w2[sub + 24];

    float sA1 = dot4(a0, w1_0) + dot4(a1, w1_1) + dot4(a2, w1_2) + dot4(a3, w1_3);
    float sA2 = dot4(a0, w2_0) + dot4(a1, w2_1) + dot4(a2, w2_2) + dot4(a3, w2_3);
    float sB1 = dot4(b0, w1_0) + dot4(b1, w1_1) + dot4(b2, w1_2) + dot4(b3, w1_3);
    float sB2 = dot4(b0, w2_0) + dot4(b1, w2_1) + dot4(b2, w2_2) + dot4(b3, w2_3);

    #pragma unroll
    for (int off = 4; off > 0; off >>= 1) {
        sA1 += __shfl_xor_sync(0xFFFFFFFF, sA1, off);
        sA2 += __shfl_xor_sync(0xFFFFFFFF, sA2, off);
        sB1 += __shfl_xor_sync(0xFFFFFFFF, sB1, off);
        sB2 += __shfl_xor_sync(0xFFFFFFFF, sB2, off);
    }

    if (sub == 0) {
        d_pack[rowA] = __floats2half2_rn(sA1, sA2);
        d_pack[rowB] = __floats2half2_rn(sB1, sB2);
    }
}

#define CLAMP(v) min(max((v), 0), MAX_NODES - 1)

// Kernel 2 (exact R9 best): cp.async.bulk table fill, indices prefetched
// before the mbarrier wait, pure-LDS gathers after.
__global__ void __launch_bounds__(1024, 1)
edge_kernel_pack(const int* __restrict__ ei,
                 float* __restrict__ out,
                 int n_edges) {
    extern __shared__ __align__(16) unsigned char smem_raw[];
    __half2* s_p = reinterpret_cast<__half2*>(smem_raw);

    uint32_t smem_base;
    asm("{ .reg .u64 t; cvta.to.shared.u64 t, %1; cvt.u32.u64 %0, t; }"
        : "=r"(smem_base) : "l"(smem_raw));
    uint32_t mbar = smem_base + TABLE_BYTES;

    int tid = threadIdx.x;

    if (tid == 0) {
        asm volatile("mbarrier.init.shared.b64 [%0], 1;" :: "r"(mbar) : "memory");
    }
    __syncthreads();

    if (tid == 0) {
        asm volatile("mbarrier.arrive.expect_tx.shared.b64 _, [%0], %1;"
                     :: "r"(mbar), "r"((uint32_t)TABLE_BYTES) : "memory");
        const char* src = reinterpret_cast<const char*>(d_pack);
        #pragma unroll
        for (int c = 0; c < 4; c++) {
            asm volatile(
                "cp.async.bulk.shared::cta.global.mbarrier::complete_tx::bytes "
                "[%0], [%1], %2, [%3];"
                :: "r"(smem_base + c * FILL_CHUNK), "l"(src + (size_t)c * FILL_CHUNK),
                   "r"((uint32_t)FILL_CHUNK), "r"(mbar) : "memory");
        }
    }

    // ---- Prefetch ALL edge indices (overlaps the bulk fill) ----
    int total_quads = n_edges >> 2;                   // 160000
    int qpb = (total_quads + gridDim.x - 1) / gridDim.x;
    int q_start = blockIdx.x * qpb;
    int q_end = min(q_start + qpb, total_quads);

    int  qs[QUADS_PER_THREAD];
    bool qv[QUADS_PER_THREAD];
    int4 sA[QUADS_PER_THREAD], dA[QUADS_PER_THREAD];
    #pragma unroll
    for (int k = 0; k < QUADS_PER_THREAD; k++) {
        int q = q_start + tid + k * 1024;
        qs[k] = q;
        qv[k] = q < q_end;
        if (qv[k]) {
            sA[k] = *reinterpret_cast<const int4*>(ei + q * 4);
            dA[k] = *reinterpret_cast<const int4*>(ei + n_edges + q * 4);
        }
    }

    // ---- Wait for the table ----
    {
        uint32_t done;
        asm volatile(
            "{\n\t"
            ".reg .pred p;\n\t"
            "mbarrier.try_wait.parity.acquire.cta.shared::cta.b64 p, [%1], 0;\n\t"
            "selp.b32 %0, 1, 0, p;\n\t"
            "}"
            : "=r"(done) : "r"(mbar) : "memory");
        if (!done) {
            asm volatile(
                "{\n\t"
                ".reg .pred P1;\n\t"
                "WL_%=:\n\t"
                "mbarrier.try_wait.parity.acquire.cta.shared::cta.b64 P1, [%0], 0, 0x989680;\n\t"
                "@P1 bra.uni WD_%=;\n\t"
                "bra.uni WL_%=;\n\t"
                "WD_%=:\n\t"
                "}"
                :: "r"(mbar) : "memory");
        }
    }

    // ---- Gather + store ----
    #pragma unroll
    for (int k = 0; k < QUADS_PER_THREAD; k++) {
        if (qv[k]) {
            float4 r;
            r.x = __low2float(s_p[CLAMP(sA[k].x)]) + __high2float(s_p[CLAMP(dA[k].x)]);
            r.y = __low2float(s_p[CLAMP(sA[k].y)]) + __high2float(s_p[CLAMP(dA[k].y)]);
            r.z = __low2float(s_p[CLAMP(sA[k].z)]) + __high2float(s_p[CLAMP(dA[k].z)]);
            r.w = __low2float(s_p[CLAMP(sA[k].w)]) + __high2float(s_p[CLAMP(dA[k].w)]);
            *reinterpret_cast<float4*>(out + qs[k] * 4) = r;
        }
    }

    // Scalar tail (n_edges % 4 != 0) — block 0 only.
    if (blockIdx.x == 0) {
        for (int e = total_quads * 4 + tid; e < n_edges; e += blockDim.x) {
            int s = CLAMP(ei[e]);
            int d = CLAMP(ei[n_edges + e]);
            out[e] = __low2float(s_p[s]) + __high2float(s_p[d]);
        }
    }
}

extern "C" void kernel_launch(void* const* d_in, const int* in_sizes, int n_in,
                              void* d_out, int out_size) {
    const float* X  = (const float*)d_in[0];
    const int*   ei = (const int*)d_in[1];     // [2, E] int32
    const float* W1 = (const float*)d_in[2];
    const float* W2 = (const float*)d_in[3];
    float* out = (float*)d_out;

    int n_nodes = in_sizes[0] / D;             // 50000
    int n_edges = in_sizes[1] / 2;             // 640000

    static int inited = 0;
    if (!inited) {
        inited = 1;
        cudaFuncSetAttribute(edge_kernel_pack,
                             cudaFuncAttributeMaxDynamicSharedMemorySize,
                             TABLE_BYTES + 16);
        // Pin BOTH kernels to the max-shared carveout so the per-SM L1/SMEM
        // split never reconfigures between alternating launches in the
        // replayed graph (suspected hidden cost in the edge kernel's ramp).
        cudaFuncSetAttribute(edge_kernel_pack,
                             cudaFuncAttributePreferredSharedMemoryCarveout, 100);
        cudaFuncSetAttribute(node_proj_kernel,
                             cudaFuncAttributePreferredSharedMemoryCarveout, 100);
    }

    // Kernel 1: 8 rows/warp, 256 threads/block = 64 rows/block (782 blocks).
    int threads1 = 256;
    int blocks1 = (n_nodes + 63) / 64;
    node_proj_kernel<<<blocks1, threads1>>>(X, W1, W2, n_nodes);

    // Kernel 2: one block per SM; table + mbarrier in smem.
    size_t smem = TABLE_BYTES + 16;
    edge_kernel_pack<<<EDGE_BLOCKS, 1024, smem>>>(ei, out, n_edges);
}